// round 5
// baseline (speedup 1.0000x reference)
#include <cuda_runtime.h>

#define KK 16
#define LL 64
#define BB 32768
#define ROWF4 256   // 64 digits * 4 float4 per element row

// Block = 64 threads: warp 0 = add role, warp 1 = sub role, sharing 32 elements.
__global__ __launch_bounds__(64, 8) void bitop_kernel(
    const float4* __restrict__ op1, const float4* __restrict__ op2,
    float4* __restrict__ outa, float4* __restrict__ outs)
{
    // double-buffered input staging [buf][tensor][elem][slot], rows padded to 5
    __shared__ float4 sin[2][2][32][5];
    // per-warp output staging
    __shared__ float4 sout[2][32][5];

    const int tid = threadIdx.x;
    const int w   = tid >> 5;       // 0 = add, 1 = sub
    const int ln  = tid & 31;
    const int ebase = blockIdx.x * 32;

    // cooperative staging role: thread covers elements g0 and g0+16, slot k
    const int k  = tid & 3;
    const int g0 = tid >> 2;        // 0..15 across the whole block

    const size_t rowA = (size_t)(ebase + g0)      * ROWF4;
    const size_t rowB = (size_t)(ebase + g0 + 16) * ROWF4;

    // own-element row for stores
    const int eo = ln >> 2;         // 0..7
    const int ks = ln & 3;
    size_t orow[4];
    #pragma unroll
    for (int r = 0; r < 4; ++r)
        orow[r] = (size_t)(ebase + eo + 8 * r) * ROWF4;

    float4* const optr = (w == 0) ? outa : outs;

    // ---- prologue: stage digit 0 into buffer 0 ----
    sin[0][0][g0][k]      = op1[rowA + k];
    sin[0][1][g0][k]      = op2[rowA + k];
    sin[0][0][g0 + 16][k] = op1[rowB + k];
    sin[0][1][g0 + 16][k] = op2[rowB + k];
    __syncthreads();

    float st = 0.f;                 // carry1 (w=0) or borrow1 (w=1)
    int buf = 0;
    float4 pf[4];

    #pragma unroll 1
    for (int l = 0; l < LL; ++l) {
        // 1. read own element's digit from smem (conflict-free: row stride 20 banks)
        float4 A0 = sin[buf][0][ln][0], A1 = sin[buf][0][ln][1],
               A2 = sin[buf][0][ln][2], A3 = sin[buf][0][ln][3];
        float4 B0 = sin[buf][1][ln][0], B1 = sin[buf][1][ln][1],
               B2 = sin[buf][1][ln][2], B3 = sin[buf][1][ln][3];

        // 2. prefetch next digit (coalesced); latency hidden by compute
        if (l < LL - 1) {
            const size_t off = (size_t)(l + 1) * 4 + k;
            pf[0] = op1[rowA + off];
            pf[1] = op2[rowA + off];
            pf[2] = op1[rowB + off];
            pf[3] = op2[rowB + off];
        }

        float a[16] = {A0.x,A0.y,A0.z,A0.w, A1.x,A1.y,A1.z,A1.w,
                       A2.x,A2.y,A2.z,A2.w, A3.x,A3.y,A3.z,A3.w};
        float c[16] = {B0.x,B0.y,B0.z,B0.w, B1.x,B1.y,B1.z,B1.w,
                       B2.x,B2.y,B2.z,B2.w, B3.x,B3.y,B3.z,B3.w};

        // 3. role-specific cyclic conv/corr (warp-uniform branch)
        float Q[16];
        #pragma unroll
        for (int v = 0; v < 16; ++v) Q[v] = 0.f;

        if (w == 0) {
            #pragma unroll
            for (int i = 0; i < 16; ++i)
                #pragma unroll
                for (int j = 0; j < 16; ++j)
                    Q[(i + j) & 15] = fmaf(a[i], c[j], Q[(i + j) & 15]);
        } else {
            #pragma unroll
            for (int i = 0; i < 16; ++i)
                #pragma unroll
                for (int j = 0; j < 16; ++j)
                    Q[(i - j + 16) & 15] = fmaf(a[i], c[j], Q[(i - j + 16) & 15]);
        }

        float Csuf[16];
        Csuf[15] = c[15];
        #pragma unroll
        for (int m = 14; m >= 1; --m) Csuf[m] = Csuf[m + 1] + c[m];

        float S = 0.f;
        if (w == 0) {
            #pragma unroll
            for (int i = 1; i < 16; ++i) S = fmaf(a[i], Csuf[16 - i], S); // P(i+j>=16)
        } else {
            #pragma unroll
            for (int i = 0; i < 15; ++i) S = fmaf(a[i], Csuf[i + 1], S);  // P(i<j)
        }

        float r[16];
        #pragma unroll
        for (int v = 0; v < 16; ++v) {
            const int vv = (w == 0) ? ((v + 15) & 15) : ((v + 1) & 15);
            r[v] = fmaf(st, Q[vv] - Q[v], Q[v]);
        }
        st = fmaf(st, (w == 0) ? Q[15] : Q[0], S);

        // 4. results -> per-warp staging
        sout[w][ln][0] = make_float4(r[0],  r[1],  r[2],  r[3]);
        sout[w][ln][1] = make_float4(r[4],  r[5],  r[6],  r[7]);
        sout[w][ln][2] = make_float4(r[8],  r[9],  r[10], r[11]);
        sout[w][ln][3] = make_float4(r[12], r[13], r[14], r[15]);
        __syncwarp();

        // 5. coalesced stores of this warp's 32 elements
        const size_t soff = (size_t)l * 4 + ks;
        #pragma unroll
        for (int rr = 0; rr < 4; ++rr)
            optr[orow[rr] + soff] = sout[w][eo + 8 * rr][ks];

        // 6. stage prefetched digit into the other buffer, flip
        if (l < LL - 1) {
            sin[buf ^ 1][0][g0][k]      = pf[0];
            sin[buf ^ 1][1][g0][k]      = pf[1];
            sin[buf ^ 1][0][g0 + 16][k] = pf[2];
            sin[buf ^ 1][1][g0 + 16][k] = pf[3];
        }
        __syncthreads();
        buf ^= 1;
    }
}

extern "C" void kernel_launch(void* const* d_in, const int* in_sizes, int n_in,
                              void* d_out, int out_size)
{
    const float4* op1 = (const float4*)d_in[0];
    const float4* op2 = (const float4*)d_in[1];
    float* out = (float*)d_out;
    float4* outa = (float4*)out;
    float4* outs = (float4*)(out + (size_t)BB * LL * KK);

    bitop_kernel<<<BB / 32, 64>>>(op1, op2, outa, outs);
}